// round 2
// baseline (speedup 1.0000x reference)
#include <cuda_runtime.h>
#include <math.h>

// Problem constants
#define BQ 2
#define SQ 2048
#define HH 2048
#define NH 16
#define HD 128

static const int M_TOK = BQ * SQ;  // 4096

// ---------------------------------------------------------------------------
// Scratch (device globals: allocation-free, graph-capture safe)
// ---------------------------------------------------------------------------
__device__ float g_q [BQ * NH * SQ * HD];            // 33.5 MB  [b,h,s,d]
__device__ float g_k [BQ * NH * SQ * HD];            // 33.5 MB  [b,h,s,d]
__device__ float g_vT[BQ * NH * HD * SQ];            // 33.5 MB  [b,h,d,s]
__device__ float g_sc[(size_t)BQ * NH * SQ * SQ];    // 536 MB   [b,h,q,k]

// ---------------------------------------------------------------------------
// Shared GEMM-NT tile body (double-buffered smem + register prefetch):
//   acc[i][j] += sum_k At[m, k] * Bt[n, k]
// Tile 128x128, BK=8, 256 threads, 8x8 per-thread register tile.
// At points at row m0 of A (row-major, leading dim lda).
// Bt points at row n0 of B (row-major, leading dim ldb).
// kdim must be a multiple of 8 (always true here: 2048 or 128).
// ---------------------------------------------------------------------------
__device__ __forceinline__ void gemm128(const float* __restrict__ At, long long lda,
                                        const float* __restrict__ Bt, long long ldb,
                                        int kdim, float (&acc)[8][8])
{
    __shared__ float As[2][8 * 128];
    __shared__ float Bs[2][8 * 128];
    const int tid = threadIdx.x;
    const int tr  = tid >> 4;        // 0..15
    const int tc  = tid & 15;        // 0..15
    const int lr  = tid >> 1;        // 0..127  (tile row for loads)
    const int lc  = (tid & 1) * 4;   // 0 or 4  (k offset for loads)

    const float* aPtr = At + (long long)lr * lda + lc;
    const float* bPtr = Bt + (long long)lr * ldb + lc;

    // Preload tile 0 into buffer 0.
    {
        float4 a4 = *reinterpret_cast<const float4*>(aPtr);
        float4 b4 = *reinterpret_cast<const float4*>(bPtr);
        As[0][(lc + 0) * 128 + lr] = a4.x;
        As[0][(lc + 1) * 128 + lr] = a4.y;
        As[0][(lc + 2) * 128 + lr] = a4.z;
        As[0][(lc + 3) * 128 + lr] = a4.w;
        Bs[0][(lc + 0) * 128 + lr] = b4.x;
        Bs[0][(lc + 1) * 128 + lr] = b4.y;
        Bs[0][(lc + 2) * 128 + lr] = b4.z;
        Bs[0][(lc + 3) * 128 + lr] = b4.w;
    }
    __syncthreads();

    const int ntiles = kdim >> 3;
    int buf = 0;

    for (int t = 0; t < ntiles; t++) {
        // Prefetch next K-step from global into registers (latency overlapped
        // with the FFMA block below).
        float4 na, nb;
        const bool more = (t + 1 < ntiles);
        if (more) {
            na = *reinterpret_cast<const float4*>(aPtr + (long long)(t + 1) * 8);
            nb = *reinterpret_cast<const float4*>(bPtr + (long long)(t + 1) * 8);
        }

        // Compute current K-step from smem buffer `buf`.
#pragma unroll
        for (int kk = 0; kk < 8; kk++) {
            float4 ra0 = *reinterpret_cast<const float4*>(&As[buf][kk * 128 + tr * 8]);
            float4 ra1 = *reinterpret_cast<const float4*>(&As[buf][kk * 128 + tr * 8 + 4]);
            float4 rb0 = *reinterpret_cast<const float4*>(&Bs[buf][kk * 128 + tc * 8]);
            float4 rb1 = *reinterpret_cast<const float4*>(&Bs[buf][kk * 128 + tc * 8 + 4]);
            float ra[8] = {ra0.x, ra0.y, ra0.z, ra0.w, ra1.x, ra1.y, ra1.z, ra1.w};
            float rb[8] = {rb0.x, rb0.y, rb0.z, rb0.w, rb1.x, rb1.y, rb1.z, rb1.w};
#pragma unroll
            for (int i = 0; i < 8; i++)
#pragma unroll
                for (int j = 0; j < 8; j++)
                    acc[i][j] += ra[i] * rb[j];
        }

        // Stage the prefetched step into the other buffer.
        if (more) {
            const int nb_ = buf ^ 1;
            As[nb_][(lc + 0) * 128 + lr] = na.x;
            As[nb_][(lc + 1) * 128 + lr] = na.y;
            As[nb_][(lc + 2) * 128 + lr] = na.z;
            As[nb_][(lc + 3) * 128 + lr] = na.w;
            Bs[nb_][(lc + 0) * 128 + lr] = nb.x;
            Bs[nb_][(lc + 1) * 128 + lr] = nb.y;
            Bs[nb_][(lc + 2) * 128 + lr] = nb.z;
            Bs[nb_][(lc + 3) * 128 + lr] = nb.w;
            __syncthreads();
        }
        buf ^= 1;
    }
}

// ---------------------------------------------------------------------------
// QKV projection: Y = X @ W^T + b, scattered into per-head layout.
// MODE 0 -> g_q [b,h,s,d], MODE 1 -> g_k [b,h,s,d], MODE 2 -> g_vT [b,h,d,s]
// ---------------------------------------------------------------------------
template <int MODE>
__global__ __launch_bounds__(256)
void k_qkv(const float* __restrict__ X, const float* __restrict__ W,
           const float* __restrict__ bias)
{
    const int m0 = blockIdx.y * 128;
    const int n0 = blockIdx.x * 128;
    float acc[8][8] = {};
    gemm128(X + (long long)m0 * HH, HH, W + (long long)n0 * HH, HH, HH, acc);

    const int tr = threadIdx.x >> 4;
    const int tc = threadIdx.x & 15;
#pragma unroll
    for (int i = 0; i < 8; i++) {
        const int m = m0 + tr * 8 + i;
        const int b = m >> 11;          // m / 2048
        const int s = m & 2047;
#pragma unroll
        for (int j = 0; j < 8; j++) {
            const int n    = n0 + tc * 8 + j;
            const int head = n >> 7;    // n / 128
            const int jd   = n & 127;
            const float v  = acc[i][j] + bias[n];
            const long long bh = (long long)(b * NH + head);
            if (MODE == 0)
                g_q[(bh * SQ + s) * HD + jd] = v;
            else if (MODE == 1)
                g_k[(bh * SQ + s) * HD + jd] = v;
            else
                g_vT[(bh * HD + jd) * SQ + s] = v;
        }
    }
}

// ---------------------------------------------------------------------------
// RoPE (in place on g_q / g_k), float4-vectorized: each thread handles 4
// consecutive rotation pairs (i, i+64), i in [0,64). blockIdx.y selects q/k.
// Matches reference fp32 rounding: inv_freq fp32, ang = s * inv_freq fp32.
// ---------------------------------------------------------------------------
__global__ __launch_bounds__(256)
void k_rope()
{
    const long long total = (long long)BQ * NH * SQ * (HD / 8);  // 4 pairs/thread
    long long idx = (long long)blockIdx.x * blockDim.x + threadIdx.x;
    if (idx >= total) return;
    const int i0 = (int)(idx & 15) * 4;      // 0,4,...,60
    const long long t = idx >> 4;            // bh * SQ + s
    const int s  = (int)(t & 2047);

    float* base = (blockIdx.y == 0 ? g_q : g_k) + t * HD;

    const float log2_base = 13.287712379549449f;   // log2(10000)
    float c[4], sn[4];
#pragma unroll
    for (int u = 0; u < 4; u++) {
        const float invf = exp2f(-log2_base * ((float)(i0 + u) * (1.0f / 64.0f)));
        const float ang  = (float)s * invf;
        c[u]  = cosf(ang);
        sn[u] = sinf(ang);
    }

    float4 x1 = *reinterpret_cast<float4*>(base + i0);
    float4 x2 = *reinterpret_cast<float4*>(base + i0 + 64);
    float4 y1, y2;
    y1.x = x1.x * c[0] - x2.x * sn[0];  y2.x = x2.x * c[0] + x1.x * sn[0];
    y1.y = x1.y * c[1] - x2.y * sn[1];  y2.y = x2.y * c[1] + x1.y * sn[1];
    y1.z = x1.z * c[2] - x2.z * sn[2];  y2.z = x2.z * c[2] + x1.z * sn[2];
    y1.w = x1.w * c[3] - x2.w * sn[3];  y2.w = x2.w * c[3] + x1.w * sn[3];
    *reinterpret_cast<float4*>(base + i0)      = y1;
    *reinterpret_cast<float4*>(base + i0 + 64) = y2;
}

// ---------------------------------------------------------------------------
// Scores: for each z = b*16+h: S = (Q @ K^T) / sqrt(d)
// ---------------------------------------------------------------------------
__global__ __launch_bounds__(256)
void k_scores()
{
    const int z  = blockIdx.z;
    const int m0 = blockIdx.y * 128;
    const int n0 = blockIdx.x * 128;
    const float* Q  = g_q + (long long)z * SQ * HD;
    const float* Kp = g_k + (long long)z * SQ * HD;
    float acc[8][8] = {};
    gemm128(Q + (long long)m0 * HD, HD, Kp + (long long)n0 * HD, HD, HD, acc);

    const int tr = threadIdx.x >> 4;
    const int tc = threadIdx.x & 15;
    float* C = g_sc + (long long)z * SQ * SQ;
    const float scale = 0.08838834764831845f;  // 1/sqrt(128)
#pragma unroll
    for (int i = 0; i < 8; i++) {
        const long long m = m0 + tr * 8 + i;
#pragma unroll
        for (int j = 0; j < 8; j++)
            C[m * SQ + (n0 + tc * 8 + j)] = acc[i][j] * scale;
    }
}

// ---------------------------------------------------------------------------
// Row softmax, in place on g_sc. One 256-thread block per row of 2048.
// ---------------------------------------------------------------------------
__global__ __launch_bounds__(256)
void k_softmax()
{
    const long long row = blockIdx.x;
    float* p = g_sc + row * SQ;
    const int tid = threadIdx.x;
    __shared__ float red[256];

    float v[8];
    float mx = -INFINITY;
#pragma unroll
    for (int i = 0; i < 8; i++) {
        v[i] = p[tid + i * 256];
        mx = fmaxf(mx, v[i]);
    }
    red[tid] = mx;
    __syncthreads();
    for (int s = 128; s > 0; s >>= 1) {
        if (tid < s) red[tid] = fmaxf(red[tid], red[tid + s]);
        __syncthreads();
    }
    mx = red[0];
    __syncthreads();

    float sum = 0.0f;
#pragma unroll
    for (int i = 0; i < 8; i++) {
        v[i] = expf(v[i] - mx);
        sum += v[i];
    }
    red[tid] = sum;
    __syncthreads();
    for (int s = 128; s > 0; s >>= 1) {
        if (tid < s) red[tid] += red[tid + s];
        __syncthreads();
    }
    const float inv = 1.0f / red[0];
#pragma unroll
    for (int i = 0; i < 8; i++)
        p[tid + i * 256] = v[i] * inv;
}

// ---------------------------------------------------------------------------
// PV: ctx = P @ V  (V stored transposed so this is NT again).
// Writes directly into final [b, s, h*d] output layout.
// ---------------------------------------------------------------------------
__global__ __launch_bounds__(256)
void k_pv(float* __restrict__ out)
{
    const int z    = blockIdx.z;
    const int b    = z >> 4;
    const int head = z & 15;
    const int m0   = blockIdx.y * 128;
    const float* P  = g_sc + (long long)z * SQ * SQ;
    const float* Vt = g_vT + (long long)z * HD * SQ;
    float acc[8][8] = {};
    gemm128(P + (long long)m0 * SQ, SQ, Vt, SQ, SQ, acc);

    const int tr = threadIdx.x >> 4;
    const int tc = threadIdx.x & 15;
#pragma unroll
    for (int i = 0; i < 8; i++) {
        const long long m = m0 + tr * 8 + i;
#pragma unroll
        for (int j = 0; j < 8; j++) {
            const int n = tc * 8 + j;  // 0..127 (head dim)
            out[((long long)b * SQ + m) * HH + head * HD + n] = acc[i][j];
        }
    }
}

// ---------------------------------------------------------------------------
// Launch
// ---------------------------------------------------------------------------
extern "C" void kernel_launch(void* const* d_in, const int* in_sizes, int n_in,
                              void* d_out, int out_size)
{
    const float* X  = (const float*)d_in[0];
    const float* Wq = (const float*)d_in[1];
    const float* bq = (const float*)d_in[2];
    const float* Wk = (const float*)d_in[3];
    const float* bk = (const float*)d_in[4];
    const float* Wv = (const float*)d_in[5];
    const float* bv = (const float*)d_in[6];
    float* out = (float*)d_out;

    // 1) QKV projections (4096 x 2048 x 2048 each)
    dim3 gProj(HH / 128, M_TOK / 128);          // (16, 32)
    k_qkv<0><<<gProj, 256>>>(X, Wq, bq);
    k_qkv<1><<<gProj, 256>>>(X, Wk, bk);
    k_qkv<2><<<gProj, 256>>>(X, Wv, bv);

    // 2) RoPE on q and k (grid.y: 0 = q, 1 = k)
    const long long ropeN = (long long)BQ * NH * SQ * (HD / 8);  // 1,048,576
    dim3 gRope((unsigned)((ropeN + 255) / 256), 2);
    k_rope<<<gRope, 256>>>();

    // 3) Scores (32 batched 2048 x 2048 x 128)
    dim3 gSc(SQ / 128, SQ / 128, BQ * NH);      // (16, 16, 32)
    k_scores<<<gSc, 256>>>();

    // 4) Softmax over rows
    k_softmax<<<BQ * NH * SQ, 256>>>();         // 65536 blocks

    // 5) PV (32 batched 2048 x 128 x 2048) -> final output layout
    dim3 gPv(1, SQ / 128, BQ * NH);             // (1, 16, 32)
    k_pv<<<gPv, 256>>>(out);
}

// round 6
// speedup vs baseline: 2.6457x; 2.6457x over previous
#include <cuda_runtime.h>
#include <cuda_bf16.h>
#include <math.h>
#include <stdint.h>

// Problem constants
#define BQ 2
#define SQ 2048
#define HH 2048
#define NH 16
#define HD 128

// ---------------------------------------------------------------------------
// Scratch (device globals: allocation-free, graph-capture safe)
// ---------------------------------------------------------------------------
__device__ float g_q [BQ * NH * SQ * HD];            // [b,h,s,d]
__device__ float g_k [BQ * NH * SQ * HD];            // [b,h,s,d]
__device__ float g_vT[BQ * NH * HD * SQ];            // [b,h,d,s]
__device__ float g_sc[(size_t)BQ * NH * SQ * SQ];    // [b,h,q,k]

// ---------------------------------------------------------------------------
// Helpers
// ---------------------------------------------------------------------------
__device__ __forceinline__ uint32_t smem_u32(const void* p) {
    uint32_t a;
    asm("{ .reg .u64 t; cvta.to.shared.u64 t, %1; cvt.u32.u64 %0, t; }" : "=r"(a) : "l"(p));
    return a;
}

#define LDSM4(r, addr) \
    asm volatile("ldmatrix.sync.aligned.m8n8.x4.shared.b16 {%0,%1,%2,%3}, [%4];" \
        : "=r"((r)[0]), "=r"((r)[1]), "=r"((r)[2]), "=r"((r)[3]) : "r"(addr))

#define MMA16816(c, a, b0, b1) \
    asm volatile("mma.sync.aligned.m16n8k16.row.col.f32.bf16.bf16.f32 " \
        "{%0,%1,%2,%3}, {%4,%5,%6,%7}, {%8,%9}, {%0,%1,%2,%3};" \
        : "+f"((c)[0]), "+f"((c)[1]), "+f"((c)[2]), "+f"((c)[3]) \
        : "r"((a)[0]), "r"((a)[1]), "r"((a)[2]), "r"((a)[3]), "r"(b0), "r"(b1))

__device__ __forceinline__ uint32_t bf2bits(__nv_bfloat162 v) {
    return *reinterpret_cast<uint32_t*>(&v);
}

// ---------------------------------------------------------------------------
// SMEM layout: 4 operand tiles, 128 rows x 64 bf16, row stride 144 B (72 bf16).
// Padding makes ldmatrix row addresses conflict-free and keeps 16 B alignment.
// ---------------------------------------------------------------------------
#define STRB 144
#define OFF_AHI 0
#define OFF_ALO 18432
#define OFF_BHI 36864
#define OFF_BLO 55296
#define SM_BYTES 73728

// Convert one float4 to hi/lo bf16 pairs and store 8 B each.
__device__ __forceinline__ void cvt_store(float4 a, unsigned char* smem,
                                          int hiBase, int loBase, uint32_t off)
{
    __nv_bfloat162 h01 = __float22bfloat162_rn(make_float2(a.x, a.y));
    __nv_bfloat162 h23 = __float22bfloat162_rn(make_float2(a.z, a.w));
    float2 r01 = make_float2(a.x - __bfloat162float(h01.x), a.y - __bfloat162float(h01.y));
    float2 r23 = make_float2(a.z - __bfloat162float(h23.x), a.w - __bfloat162float(h23.y));
    __nv_bfloat162 l01 = __float22bfloat162_rn(r01);
    __nv_bfloat162 l23 = __float22bfloat162_rn(r23);
    *reinterpret_cast<uint2*>(smem + hiBase + off) = make_uint2(bf2bits(h01), bf2bits(h23));
    *reinterpret_cast<uint2*>(smem + loBase + off) = make_uint2(bf2bits(l01), bf2bits(l23));
}

// ---------------------------------------------------------------------------
// Warp-MMA GEMM-NT: acc[i][j][] += A(128,k) @ B(128,k)^T on a 128x128 tile.
// 256 threads, 8 warps (2 m x 4 n), per-warp 64x32, split-bf16 3-pass.
// kdim multiple of 64. acc layout: [m-tile][n-tile][c0..c3] per mma fragment.
// ---------------------------------------------------------------------------
__device__ __forceinline__ void wgemm(const float* __restrict__ At, long long lda,
                                      const float* __restrict__ Bt, long long ldb,
                                      int kdim, float (&acc)[4][4][4])
{
    extern __shared__ unsigned char smem[];
    const int tid  = threadIdx.x;
    const int lane = tid & 31;
    const int warp = tid >> 5;
    const int wm0  = (warp >> 2) * 64;
    const int wn0  = (warp & 3) * 32;
    const uint32_t sb = smem_u32(smem);

    // ldmatrix per-lane address components
    const int mat = lane >> 3;
    const int la7 = lane & 7;
    const uint32_t aBaseHi = sb + OFF_AHI + (wm0 + (mat & 1) * 8 + la7) * STRB + ((mat >> 1) * 8) * 2;
    const uint32_t aBaseLo = aBaseHi + (OFF_ALO - OFF_AHI);
    const uint32_t bBaseHi = sb + OFF_BHI + (wn0 + (mat >> 1) * 8 + la7) * STRB + ((mat & 1) * 8) * 2;
    const uint32_t bBaseLo = bBaseHi + (OFF_BLO - OFF_BHI);

    // Global-load mapping: 8 float4 per operand per thread per 64-K block.
    int rowArr[8], colArr[8];
#pragma unroll
    for (int it = 0; it < 8; it++) {
        int idx = it * 256 + tid;
        rowArr[it] = idx >> 4;
        colArr[it] = (idx & 15) << 2;
    }

    float4 pa[8], pb[8];
#pragma unroll
    for (int it = 0; it < 8; it++) {
        pa[it] = *reinterpret_cast<const float4*>(At + (long long)rowArr[it] * lda + colArr[it]);
        pb[it] = *reinterpret_cast<const float4*>(Bt + (long long)rowArr[it] * ldb + colArr[it]);
    }

    const int nkb = kdim >> 6;
    for (int kb = 0; kb < nkb; kb++) {
        // Stage current block (hi/lo split) into smem.
#pragma unroll
        for (int it = 0; it < 8; it++) {
            uint32_t off = (uint32_t)(rowArr[it] * STRB + colArr[it] * 2);
            cvt_store(pa[it], smem, OFF_AHI, OFF_ALO, off);
            cvt_store(pb[it], smem, OFF_BHI, OFF_BLO, off);
        }
        __syncthreads();

        // Prefetch next block (overlaps with compute below).
        if (kb + 1 < nkb) {
            const long long koff = (long long)(kb + 1) * 64;
#pragma unroll
            for (int it = 0; it < 8; it++) {
                pa[it] = *reinterpret_cast<const float4*>(At + (long long)rowArr[it] * lda + koff + colArr[it]);
                pb[it] = *reinterpret_cast<const float4*>(Bt + (long long)rowArr[it] * ldb + koff + colArr[it]);
            }
        }

        // Compute 4 k16 steps.
#pragma unroll
        for (int kk = 0; kk < 4; kk++) {
            uint32_t AH[4][4], AL[4][4];
#pragma unroll
            for (int i = 0; i < 4; i++) {
                LDSM4(AH[i], aBaseHi + i * (16 * STRB) + kk * 32);
                LDSM4(AL[i], aBaseLo + i * (16 * STRB) + kk * 32);
            }
            uint32_t BH[2][4], BL[2][4];
#pragma unroll
            for (int jj = 0; jj < 2; jj++) {
                LDSM4(BH[jj], bBaseHi + jj * (16 * STRB) + kk * 32);
                LDSM4(BL[jj], bBaseLo + jj * (16 * STRB) + kk * 32);
            }
#pragma unroll
            for (int i = 0; i < 4; i++) {
#pragma unroll
                for (int j = 0; j < 4; j++) {
                    const int jj = j >> 1, o = (j & 1) * 2;
                    MMA16816(acc[i][j], AH[i], BH[jj][o], BH[jj][o + 1]);
                    MMA16816(acc[i][j], AH[i], BL[jj][o], BL[jj][o + 1]);
                    MMA16816(acc[i][j], AL[i], BH[jj][o], BH[jj][o + 1]);
                }
            }
        }
        __syncthreads();
    }
}

// ---------------------------------------------------------------------------
// QKV projection: Y = X @ W^T + b, scattered into per-head layout.
// MODE 0 -> g_q [b,h,s,d], MODE 1 -> g_k [b,h,s,d], MODE 2 -> g_vT [b,h,d,s]
// ---------------------------------------------------------------------------
template <int MODE>
__global__ __launch_bounds__(256)
void k_qkv(const float* __restrict__ X, const float* __restrict__ W,
           const float* __restrict__ bias)
{
    extern __shared__ unsigned char smem[];
    const int tid = threadIdx.x;
    const int m0 = blockIdx.y * 128;
    const int n0 = blockIdx.x * 128;

    float acc[4][4][4];
#pragma unroll
    for (int i = 0; i < 4; i++)
#pragma unroll
        for (int j = 0; j < 4; j++)
#pragma unroll
            for (int c = 0; c < 4; c++) acc[i][j][c] = 0.0f;

    wgemm(X + (long long)m0 * HH, HH, W + (long long)n0 * HH, HH, HH, acc);

    const int lane = tid & 31, warp = tid >> 5;
    const int wm0 = (warp >> 2) * 64, wn0 = (warp & 3) * 32;
    const int g = lane >> 2, tig = lane & 3;
    const int head = n0 >> 7;                 // whole tile is one head (HD==128)

    if (MODE != 2) {
        float* base = (MODE == 0 ? g_q : g_k);
#pragma unroll
        for (int j = 0; j < 4; j++) {
            const int c0 = wn0 + j * 8 + tig * 2;
            const float bx = __ldg(bias + n0 + c0);
            const float by = __ldg(bias + n0 + c0 + 1);
#pragma unroll
            for (int i = 0; i < 4; i++) {
                const int r = wm0 + i * 16 + g;
                const int m = m0 + r;
                const int b = m >> 11, s = m & 2047;
                const long long bh = (long long)(b * NH + head);
                float* d0 = base + ((bh * SQ + s) * HD + c0);
                *reinterpret_cast<float2*>(d0) =
                    make_float2(acc[i][j][0] + bx, acc[i][j][1] + by);
                float* d1 = base + ((bh * SQ + s + 8) * HD + c0);
                *reinterpret_cast<float2*>(d1) =
                    make_float2(acc[i][j][2] + bx, acc[i][j][3] + by);
            }
        }
    } else {
        // Stage to smem, then coalesced transposed writes into g_vT.
        float* stage = reinterpret_cast<float*>(smem);
#pragma unroll
        for (int i = 0; i < 4; i++) {
#pragma unroll
            for (int j = 0; j < 4; j++) {
                const int r = wm0 + i * 16 + g;
                const int c = wn0 + j * 8 + tig * 2;
                stage[r * 129 + c]       = acc[i][j][0];
                stage[r * 129 + c + 1]   = acc[i][j][1];
                stage[(r + 8) * 129 + c] = acc[i][j][2];
                stage[(r + 8) * 129 + c + 1] = acc[i][j][3];
            }
        }
        __syncthreads();
        const int rr  = tid & 127;
        const int ch0 = (tid >> 7) * 64;
        const int m = m0 + rr, b = m >> 11, s = m & 2047;
        const long long bh = (long long)(b * NH + head);
#pragma unroll
        for (int cc = 0; cc < 64; cc++) {
            const int jd = ch0 + cc;
            g_vT[(bh * HD + jd) * SQ + s] = stage[rr * 129 + jd] + __ldg(bias + n0 + jd);
        }
    }
}

// ---------------------------------------------------------------------------
// RoPE (in place on g_q / g_k), float4-vectorized; blockIdx.y selects q/k.
// ---------------------------------------------------------------------------
__global__ __launch_bounds__(256)
void k_rope()
{
    const long long total = (long long)BQ * NH * SQ * (HD / 8);
    long long idx = (long long)blockIdx.x * blockDim.x + threadIdx.x;
    if (idx >= total) return;
    const int i0 = (int)(idx & 15) * 4;
    const long long t = idx >> 4;
    const int s  = (int)(t & 2047);

    float* base = (blockIdx.y == 0 ? g_q : g_k) + t * HD;

    const float log2_base = 13.287712379549449f;   // log2(10000)
    float c[4], sn[4];
#pragma unroll
    for (int u = 0; u < 4; u++) {
        const float invf = exp2f(-log2_base * ((float)(i0 + u) * (1.0f / 64.0f)));
        const float ang  = (float)s * invf;
        c[u]  = cosf(ang);
        sn[u] = sinf(ang);
    }
    float4 x1 = *reinterpret_cast<float4*>(base + i0);
    float4 x2 = *reinterpret_cast<float4*>(base + i0 + 64);
    float4 y1, y2;
    y1.x = x1.x * c[0] - x2.x * sn[0];  y2.x = x2.x * c[0] + x1.x * sn[0];
    y1.y = x1.y * c[1] - x2.y * sn[1];  y2.y = x2.y * c[1] + x1.y * sn[1];
    y1.z = x1.z * c[2] - x2.z * sn[2];  y2.z = x2.z * c[2] + x1.z * sn[2];
    y1.w = x1.w * c[3] - x2.w * sn[3];  y2.w = x2.w * c[3] + x1.w * sn[3];
    *reinterpret_cast<float4*>(base + i0)      = y1;
    *reinterpret_cast<float4*>(base + i0 + 64) = y2;
}

// ---------------------------------------------------------------------------
// Scores: S = (Q @ K^T) / sqrt(d) per (b,h)
// ---------------------------------------------------------------------------
__global__ __launch_bounds__(256)
void k_scores()
{
    const int tid = threadIdx.x;
    const int z  = blockIdx.z;
    const int m0 = blockIdx.y * 128;
    const int n0 = blockIdx.x * 128;
    const float* Q  = g_q + (long long)z * SQ * HD;
    const float* Kp = g_k + (long long)z * SQ * HD;

    float acc[4][4][4];
#pragma unroll
    for (int i = 0; i < 4; i++)
#pragma unroll
        for (int j = 0; j < 4; j++)
#pragma unroll
            for (int c = 0; c < 4; c++) acc[i][j][c] = 0.0f;

    wgemm(Q + (long long)m0 * HD, HD, Kp + (long long)n0 * HD, HD, HD, acc);

    const int lane = tid & 31, warp = tid >> 5;
    const int wm0 = (warp >> 2) * 64, wn0 = (warp & 3) * 32;
    const int g = lane >> 2, tig = lane & 3;
    float* C = g_sc + (long long)z * SQ * SQ;
    const float scale = 0.08838834764831845f;   // 1/sqrt(128)

#pragma unroll
    for (int i = 0; i < 4; i++) {
#pragma unroll
        for (int j = 0; j < 4; j++) {
            const int r = wm0 + i * 16 + g;
            const int c = wn0 + j * 8 + tig * 2;
            *reinterpret_cast<float2*>(C + (long long)(m0 + r) * SQ + n0 + c) =
                make_float2(acc[i][j][0] * scale, acc[i][j][1] * scale);
            *reinterpret_cast<float2*>(C + (long long)(m0 + r + 8) * SQ + n0 + c) =
                make_float2(acc[i][j][2] * scale, acc[i][j][3] * scale);
        }
    }
}

// ---------------------------------------------------------------------------
// Row softmax, in place on g_sc.
// ---------------------------------------------------------------------------
__global__ __launch_bounds__(256)
void k_softmax()
{
    const long long row = blockIdx.x;
    float* p = g_sc + row * SQ;
    const int tid = threadIdx.x;
    __shared__ float red[256];

    float v[8];
    float mx = -INFINITY;
#pragma unroll
    for (int i = 0; i < 8; i++) {
        v[i] = p[tid + i * 256];
        mx = fmaxf(mx, v[i]);
    }
    red[tid] = mx;
    __syncthreads();
    for (int s = 128; s > 0; s >>= 1) {
        if (tid < s) red[tid] = fmaxf(red[tid], red[tid + s]);
        __syncthreads();
    }
    mx = red[0];
    __syncthreads();

    float sum = 0.0f;
#pragma unroll
    for (int i = 0; i < 8; i++) {
        v[i] = expf(v[i] - mx);
        sum += v[i];
    }
    red[tid] = sum;
    __syncthreads();
    for (int s = 128; s > 0; s >>= 1) {
        if (tid < s) red[tid] += red[tid + s];
        __syncthreads();
    }
    const float inv = 1.0f / red[0];
#pragma unroll
    for (int i = 0; i < 8; i++)
        p[tid + i * 256] = v[i] * inv;
}

// ---------------------------------------------------------------------------
// PV: ctx = P @ V (V transposed -> NT), written to final [b,s,h*d] layout.
// ---------------------------------------------------------------------------
__global__ __launch_bounds__(256)
void k_pv(float* __restrict__ out)
{
    const int tid = threadIdx.x;
    const int z    = blockIdx.z;
    const int b    = z >> 4;
    const int head = z & 15;
    const int m0   = blockIdx.y * 128;
    const float* P  = g_sc + (long long)z * SQ * SQ;
    const float* Vt = g_vT + (long long)z * HD * SQ;

    float acc[4][4][4];
#pragma unroll
    for (int i = 0; i < 4; i++)
#pragma unroll
        for (int j = 0; j < 4; j++)
#pragma unroll
            for (int c = 0; c < 4; c++) acc[i][j][c] = 0.0f;

    wgemm(P + (long long)m0 * SQ, SQ, Vt, SQ, SQ, acc);

    const int lane = tid & 31, warp = tid >> 5;
    const int wm0 = (warp >> 2) * 64, wn0 = (warp & 3) * 32;
    const int g = lane >> 2, tig = lane & 3;

#pragma unroll
    for (int i = 0; i < 4; i++) {
#pragma unroll
        for (int j = 0; j < 4; j++) {
            const int r = wm0 + i * 16 + g;
            const int c = wn0 + j * 8 + tig * 2;
            *reinterpret_cast<float2*>(
                out + ((long long)b * SQ + m0 + r) * HH + head * HD + c) =
                make_float2(acc[i][j][0], acc[i][j][1]);
            *reinterpret_cast<float2*>(
                out + ((long long)b * SQ + m0 + r + 8) * HH + head * HD + c) =
                make_float2(acc[i][j][2], acc[i][j][3]);
        }
    }
}

// ---------------------------------------------------------------------------
// Launch
// ---------------------------------------------------------------------------
extern "C" void kernel_launch(void* const* d_in, const int* in_sizes, int n_in,
                              void* d_out, int out_size)
{
    const float* X  = (const float*)d_in[0];
    const float* Wq = (const float*)d_in[1];
    const float* bq = (const float*)d_in[2];
    const float* Wk = (const float*)d_in[3];
    const float* bk = (const float*)d_in[4];
    const float* Wv = (const float*)d_in[5];
    const float* bv = (const float*)d_in[6];
    float* out = (float*)d_out;

    cudaFuncSetAttribute(k_qkv<0>, cudaFuncAttributeMaxDynamicSharedMemorySize, SM_BYTES);
    cudaFuncSetAttribute(k_qkv<1>, cudaFuncAttributeMaxDynamicSharedMemorySize, SM_BYTES);
    cudaFuncSetAttribute(k_qkv<2>, cudaFuncAttributeMaxDynamicSharedMemorySize, SM_BYTES);
    cudaFuncSetAttribute(k_scores, cudaFuncAttributeMaxDynamicSharedMemorySize, SM_BYTES);
    cudaFuncSetAttribute(k_pv,     cudaFuncAttributeMaxDynamicSharedMemorySize, SM_BYTES);

    // 1) QKV projections (4096 x 2048 x 2048 each), mma.sync split-bf16
    dim3 gProj(HH / 128, (BQ * SQ) / 128);       // (16, 32)
    k_qkv<0><<<gProj, 256, SM_BYTES>>>(X, Wq, bq);
    k_qkv<1><<<gProj, 256, SM_BYTES>>>(X, Wk, bk);
    k_qkv<2><<<gProj, 256, SM_BYTES>>>(X, Wv, bv);

    // 2) RoPE on q and k
    const long long ropeN = (long long)BQ * NH * SQ * (HD / 8);
    dim3 gRope((unsigned)((ropeN + 255) / 256), 2);
    k_rope<<<gRope, 256>>>();

    // 3) Scores (32 batched 2048 x 2048 x 128)
    dim3 gSc(SQ / 128, SQ / 128, BQ * NH);       // (16, 16, 32)
    k_scores<<<gSc, 256, SM_BYTES>>>();

    // 4) Softmax over rows
    k_softmax<<<BQ * NH * SQ, 256>>>();

    // 5) PV (32 batched 2048 x 128 x 2048)
    dim3 gPv(1, SQ / 128, BQ * NH);              // (1, 16, 32)
    k_pv<<<gPv, 256, SM_BYTES>>>(out);
}

// round 8
// speedup vs baseline: 2.9456x; 1.1133x over previous
#include <cuda_runtime.h>
#include <cuda_bf16.h>
#include <math.h>
#include <stdint.h>

// Problem constants
#define BQ 2
#define SQ 2048
#define HH 2048
#define NH 16
#define HD 128

// ---------------------------------------------------------------------------
// Scratch (device globals: allocation-free, graph-capture safe)
// ---------------------------------------------------------------------------
__device__ float g_q [BQ * NH * SQ * HD];            // [b,h,s,d]
__device__ float g_k [BQ * NH * SQ * HD];            // [b,h,s,d]
__device__ float g_vT[BQ * NH * HD * SQ];            // [b,h,d,s]

// ---------------------------------------------------------------------------
// Helpers
// ---------------------------------------------------------------------------
__device__ __forceinline__ uint32_t smem_u32(const void* p) {
    uint32_t a;
    asm("{ .reg .u64 t; cvta.to.shared.u64 t, %1; cvt.u32.u64 %0, t; }" : "=r"(a) : "l"(p));
    return a;
}

#define LDSM4(r, addr) \
    asm volatile("ldmatrix.sync.aligned.m8n8.x4.shared.b16 {%0,%1,%2,%3}, [%4];" \
        : "=r"((r)[0]), "=r"((r)[1]), "=r"((r)[2]), "=r"((r)[3]) : "r"(addr))

#define MMA16816(c, a, b0, b1) \
    asm volatile("mma.sync.aligned.m16n8k16.row.col.f32.bf16.bf16.f32 " \
        "{%0,%1,%2,%3}, {%4,%5,%6,%7}, {%8,%9}, {%0,%1,%2,%3};" \
        : "+f"((c)[0]), "+f"((c)[1]), "+f"((c)[2]), "+f"((c)[3]) \
        : "r"((a)[0]), "r"((a)[1]), "r"((a)[2]), "r"((a)[3]), "r"(b0), "r"(b1))

__device__ __forceinline__ uint32_t bf2bits(__nv_bfloat162 v) {
    return *reinterpret_cast<uint32_t*>(&v);
}
__device__ __forceinline__ uint32_t packbf(float a, float b) {
    __nv_bfloat162 h = __float22bfloat162_rn(make_float2(a, b));
    return bf2bits(h);
}

// ---------------------------------------------------------------------------
// QKV GEMM smem layout: 4 tiles, 128 x 64 bf16, row stride 144 B.
// ---------------------------------------------------------------------------
#define STRB 144
#define OFF_AHI 0
#define OFF_ALO 18432
#define OFF_BHI 36864
#define OFF_BLO 55296
#define SM_QKV 73728

// Convert one float4 to hi/lo bf16 pairs and store 8 B each.
__device__ __forceinline__ void cvt_store(float4 a, unsigned char* smem,
                                          int hiBase, int loBase, uint32_t off)
{
    __nv_bfloat162 h01 = __float22bfloat162_rn(make_float2(a.x, a.y));
    __nv_bfloat162 h23 = __float22bfloat162_rn(make_float2(a.z, a.w));
    float2 r01 = make_float2(a.x - __bfloat162float(h01.x), a.y - __bfloat162float(h01.y));
    float2 r23 = make_float2(a.z - __bfloat162float(h23.x), a.w - __bfloat162float(h23.y));
    __nv_bfloat162 l01 = __float22bfloat162_rn(r01);
    __nv_bfloat162 l23 = __float22bfloat162_rn(r23);
    *reinterpret_cast<uint2*>(smem + hiBase + off) = make_uint2(bf2bits(h01), bf2bits(h23));
    *reinterpret_cast<uint2*>(smem + loBase + off) = make_uint2(bf2bits(l01), bf2bits(l23));
}

// ---------------------------------------------------------------------------
// Warp-MMA GEMM-NT (validated): 128x128 tile, 8 warps 2m x 4n.
// ---------------------------------------------------------------------------
__device__ __forceinline__ void wgemm(const float* __restrict__ At, long long lda,
                                      const float* __restrict__ Bt, long long ldb,
                                      int kdim, float (&acc)[4][4][4])
{
    extern __shared__ unsigned char smem[];
    const int tid  = threadIdx.x;
    const int lane = tid & 31;
    const int warp = tid >> 5;
    const int wm0  = (warp >> 2) * 64;
    const int wn0  = (warp & 3) * 32;
    const uint32_t sb = smem_u32(smem);

    const int mat = lane >> 3;
    const int la7 = lane & 7;
    const uint32_t aBaseHi = sb + OFF_AHI + (wm0 + (mat & 1) * 8 + la7) * STRB + ((mat >> 1) * 8) * 2;
    const uint32_t aBaseLo = aBaseHi + (OFF_ALO - OFF_AHI);
    const uint32_t bBaseHi = sb + OFF_BHI + (wn0 + (mat >> 1) * 8 + la7) * STRB + ((mat & 1) * 8) * 2;
    const uint32_t bBaseLo = bBaseHi + (OFF_BLO - OFF_BHI);

    int rowArr[8], colArr[8];
#pragma unroll
    for (int it = 0; it < 8; it++) {
        int idx = it * 256 + tid;
        rowArr[it] = idx >> 4;
        colArr[it] = (idx & 15) << 2;
    }

    float4 pa[8], pb[8];
#pragma unroll
    for (int it = 0; it < 8; it++) {
        pa[it] = *reinterpret_cast<const float4*>(At + (long long)rowArr[it] * lda + colArr[it]);
        pb[it] = *reinterpret_cast<const float4*>(Bt + (long long)rowArr[it] * ldb + colArr[it]);
    }

    const int nkb = kdim >> 6;
    for (int kb = 0; kb < nkb; kb++) {
#pragma unroll
        for (int it = 0; it < 8; it++) {
            uint32_t off = (uint32_t)(rowArr[it] * STRB + colArr[it] * 2);
            cvt_store(pa[it], smem, OFF_AHI, OFF_ALO, off);
            cvt_store(pb[it], smem, OFF_BHI, OFF_BLO, off);
        }
        __syncthreads();

        if (kb + 1 < nkb) {
            const long long koff = (long long)(kb + 1) * 64;
#pragma unroll
            for (int it = 0; it < 8; it++) {
                pa[it] = *reinterpret_cast<const float4*>(At + (long long)rowArr[it] * lda + koff + colArr[it]);
                pb[it] = *reinterpret_cast<const float4*>(Bt + (long long)rowArr[it] * ldb + koff + colArr[it]);
            }
        }

#pragma unroll
        for (int kk = 0; kk < 4; kk++) {
            uint32_t AH[4][4], AL[4][4];
#pragma unroll
            for (int i = 0; i < 4; i++) {
                LDSM4(AH[i], aBaseHi + i * (16 * STRB) + kk * 32);
                LDSM4(AL[i], aBaseLo + i * (16 * STRB) + kk * 32);
            }
            uint32_t BH[2][4], BL[2][4];
#pragma unroll
            for (int jj = 0; jj < 2; jj++) {
                LDSM4(BH[jj], bBaseHi + jj * (16 * STRB) + kk * 32);
                LDSM4(BL[jj], bBaseLo + jj * (16 * STRB) + kk * 32);
            }
#pragma unroll
            for (int i = 0; i < 4; i++) {
#pragma unroll
                for (int j = 0; j < 4; j++) {
                    const int jj = j >> 1, o = (j & 1) * 2;
                    MMA16816(acc[i][j], AH[i], BH[jj][o], BH[jj][o + 1]);
                    MMA16816(acc[i][j], AH[i], BL[jj][o], BL[jj][o + 1]);
                    MMA16816(acc[i][j], AL[i], BH[jj][o], BH[jj][o + 1]);
                }
            }
        }
        __syncthreads();
    }
}

// ---------------------------------------------------------------------------
// QKV projection (validated).
// ---------------------------------------------------------------------------
template <int MODE>
__global__ __launch_bounds__(256)
void k_qkv(const float* __restrict__ X, const float* __restrict__ W,
           const float* __restrict__ bias)
{
    extern __shared__ unsigned char smem[];
    const int tid = threadIdx.x;
    const int m0 = blockIdx.y * 128;
    const int n0 = blockIdx.x * 128;

    float acc[4][4][4];
#pragma unroll
    for (int i = 0; i < 4; i++)
#pragma unroll
        for (int j = 0; j < 4; j++)
#pragma unroll
            for (int c = 0; c < 4; c++) acc[i][j][c] = 0.0f;

    wgemm(X + (long long)m0 * HH, HH, W + (long long)n0 * HH, HH, HH, acc);

    const int lane = tid & 31, warp = tid >> 5;
    const int wm0 = (warp >> 2) * 64, wn0 = (warp & 3) * 32;
    const int g = lane >> 2, tig = lane & 3;
    const int head = n0 >> 7;

    if (MODE != 2) {
        float* base = (MODE == 0 ? g_q : g_k);
#pragma unroll
        for (int j = 0; j < 4; j++) {
            const int c0 = wn0 + j * 8 + tig * 2;
            const float bx = __ldg(bias + n0 + c0);
            const float by = __ldg(bias + n0 + c0 + 1);
#pragma unroll
            for (int i = 0; i < 4; i++) {
                const int r = wm0 + i * 16 + g;
                const int m = m0 + r;
                const int b = m >> 11, s = m & 2047;
                const long long bh = (long long)(b * NH + head);
                float* d0 = base + ((bh * SQ + s) * HD + c0);
                *reinterpret_cast<float2*>(d0) =
                    make_float2(acc[i][j][0] + bx, acc[i][j][1] + by);
                float* d1 = base + ((bh * SQ + s + 8) * HD + c0);
                *reinterpret_cast<float2*>(d1) =
                    make_float2(acc[i][j][2] + bx, acc[i][j][3] + by);
            }
        }
    } else {
        float* stage = reinterpret_cast<float*>(smem);
#pragma unroll
        for (int i = 0; i < 4; i++) {
#pragma unroll
            for (int j = 0; j < 4; j++) {
                const int r = wm0 + i * 16 + g;
                const int c = wn0 + j * 8 + tig * 2;
                stage[r * 129 + c]       = acc[i][j][0];
                stage[r * 129 + c + 1]   = acc[i][j][1];
                stage[(r + 8) * 129 + c] = acc[i][j][2];
                stage[(r + 8) * 129 + c + 1] = acc[i][j][3];
            }
        }
        __syncthreads();
        const int rr  = tid & 127;
        const int ch0 = (tid >> 7) * 64;
        const int m = m0 + rr, b = m >> 11, s = m & 2047;
        const long long bh = (long long)(b * NH + head);
#pragma unroll
        for (int cc = 0; cc < 64; cc++) {
            const int jd = ch0 + cc;
            g_vT[(bh * HD + jd) * SQ + s] = stage[rr * 129 + jd] + __ldg(bias + n0 + jd);
        }
    }
}

// ---------------------------------------------------------------------------
// RoPE (validated).
// ---------------------------------------------------------------------------
__global__ __launch_bounds__(256)
void k_rope()
{
    const long long total = (long long)BQ * NH * SQ * (HD / 8);
    long long idx = (long long)blockIdx.x * blockDim.x + threadIdx.x;
    if (idx >= total) return;
    const int i0 = (int)(idx & 15) * 4;
    const long long t = idx >> 4;
    const int s  = (int)(t & 2047);

    float* base = (blockIdx.y == 0 ? g_q : g_k) + t * HD;

    const float log2_base = 13.287712379549449f;
    float c[4], sn[4];
#pragma unroll
    for (int u = 0; u < 4; u++) {
        const float invf = exp2f(-log2_base * ((float)(i0 + u) * (1.0f / 64.0f)));
        const float ang  = (float)s * invf;
        c[u]  = cosf(ang);
        sn[u] = sinf(ang);
    }
    float4 x1 = *reinterpret_cast<float4*>(base + i0);
    float4 x2 = *reinterpret_cast<float4*>(base + i0 + 64);
    float4 y1, y2;
    y1.x = x1.x * c[0] - x2.x * sn[0];  y2.x = x2.x * c[0] + x1.x * sn[0];
    y1.y = x1.y * c[1] - x2.y * sn[1];  y2.y = x2.y * c[1] + x1.y * sn[1];
    y1.z = x1.z * c[2] - x2.z * sn[2];  y2.z = x2.z * c[2] + x1.z * sn[2];
    y1.w = x1.w * c[3] - x2.w * sn[3];  y2.w = x2.w * c[3] + x1.w * sn[3];
    *reinterpret_cast<float4*>(base + i0)      = y1;
    *reinterpret_cast<float4*>(base + i0 + 64) = y2;
}

// ---------------------------------------------------------------------------
// Fused flash attention: per (q-tile 128, bh): loop over 64-key blocks.
// Warps split m-only (16 rows each) -> online softmax warp-local.
// ---------------------------------------------------------------------------
#define STRQ 272
#define STRP 144
#define AOFF_QHI 0
#define AOFF_QLO 34816
#define AOFF_KHI 69632
#define AOFF_KLO 87040
#define AOFF_PHI 104448
#define AOFF_PLO 122880
#define AOFF_VHI 141312
#define AOFF_VLO 159744
#define SM_ATTN  178176

__global__ __launch_bounds__(256, 1)
void k_attn(float* __restrict__ out)
{
    extern __shared__ unsigned char smem[];
    const int tid  = threadIdx.x;
    const int lane = tid & 31;
    const int warp = tid >> 5;
    const int z    = blockIdx.y;
    const int b    = z >> 4;
    const int head = z & 15;
    const int m0   = blockIdx.x * 128;

    const float* Qg = g_q  + (long long)z * SQ * HD + (long long)m0 * HD;
    const float* Kg = g_k  + (long long)z * SQ * HD;
    const float* Vg = g_vT + (long long)z * HD * SQ;
    const uint32_t sb = smem_u32(smem);

    // Stage Q tile (128 x 128 fp32) as hi/lo bf16.
#pragma unroll
    for (int it = 0; it < 16; it++) {
        int idx = it * 256 + tid;
        int row = idx >> 5;
        int c4  = idx & 31;
        float4 a = *reinterpret_cast<const float4*>(Qg + row * HD + c4 * 4);
        cvt_store(a, smem, AOFF_QHI, AOFF_QLO, (uint32_t)(row * STRQ + c4 * 8));
    }

    const int mat = lane >> 3;
    const int la7 = lane & 7;
    const int g   = lane >> 2;
    const int tig = lane & 3;

    const uint32_t aQhi = sb + AOFF_QHI + (warp * 16 + (mat & 1) * 8 + la7) * STRQ + (mat >> 1) * 16;
    const uint32_t aQlo = aQhi + (AOFF_QLO - AOFF_QHI);
    const uint32_t bKhi = sb + AOFF_KHI + ((mat >> 1) * 8 + la7) * STRQ + (mat & 1) * 16;
    const uint32_t bKlo = bKhi + (AOFF_KLO - AOFF_KHI);
    const uint32_t aPhi = sb + AOFF_PHI + (warp * 16 + (mat & 1) * 8 + la7) * STRP + (mat >> 1) * 16;
    const uint32_t aPlo = aPhi + (AOFF_PLO - AOFF_PHI);
    const uint32_t bVhi = sb + AOFF_VHI + ((mat >> 1) * 8 + la7) * STRP + (mat & 1) * 16;
    const uint32_t bVlo = bVhi + (AOFF_VLO - AOFF_VHI);

    // P store addresses (this thread's fragment rows)
    const uint32_t pRow0Hi = sb + AOFF_PHI + (warp * 16 + g) * STRP + tig * 4;
    const uint32_t pRow0Lo = pRow0Hi + (AOFF_PLO - AOFF_PHI);

    float oacc[16][4];
#pragma unroll
    for (int j = 0; j < 16; j++)
#pragma unroll
        for (int c = 0; c < 4; c++) oacc[j][c] = 0.0f;
    float mrow0 = -INFINITY, mrow1 = -INFINITY;
    float lrow0 = 0.0f, lrow1 = 0.0f;
    const float scale = 0.08838834764831845f;   // 1/sqrt(128)

    for (int kb = 0; kb < SQ / 64; kb++) {
        // Load K block (64 x 128) and V^T block (128 x 64), hi/lo split.
#pragma unroll
        for (int it = 0; it < 8; it++) {
            int idx = it * 256 + tid;
            int row = idx >> 5;
            int c4  = idx & 31;
            float4 a = *reinterpret_cast<const float4*>(Kg + (long long)(kb * 64 + row) * HD + c4 * 4);
            cvt_store(a, smem, AOFF_KHI, AOFF_KLO, (uint32_t)(row * STRQ + c4 * 8));
        }
#pragma unroll
        for (int it = 0; it < 8; it++) {
            int idx = it * 256 + tid;
            int row = idx >> 4;
            int c4  = idx & 15;
            float4 a = *reinterpret_cast<const float4*>(Vg + (long long)row * SQ + kb * 64 + c4 * 4);
            cvt_store(a, smem, AOFF_VHI, AOFF_VLO, (uint32_t)(row * STRP + c4 * 8));
        }
        __syncthreads();

        // S = Q K^T (3-pass split-bf16); per warp: 16 rows x 64 keys.
        float sacc[8][4];
#pragma unroll
        for (int j = 0; j < 8; j++)
#pragma unroll
            for (int c = 0; c < 4; c++) sacc[j][c] = 0.0f;

#pragma unroll
        for (int kk = 0; kk < 8; kk++) {
            uint32_t AH[4], AL[4];
            LDSM4(AH, aQhi + kk * 32);
            LDSM4(AL, aQlo + kk * 32);
            uint32_t BH[4][4], BL[4][4];
#pragma unroll
            for (int jj = 0; jj < 4; jj++) {
                LDSM4(BH[jj], bKhi + jj * (16 * STRQ) + kk * 32);
                LDSM4(BL[jj], bKlo + jj * (16 * STRQ) + kk * 32);
            }
#pragma unroll
            for (int j = 0; j < 8; j++) {
                const int jj = j >> 1, o = (j & 1) * 2;
                MMA16816(sacc[j], AH, BH[jj][o], BH[jj][o + 1]);
                MMA16816(sacc[j], AH, BL[jj][o], BL[jj][o + 1]);
                MMA16816(sacc[j], AL, BH[jj][o], BH[jj][o + 1]);
            }
        }

        // Online softmax (rows g, g+8 of this warp's 16).
        float mx0 = -INFINITY, mx1 = -INFINITY;
#pragma unroll
        for (int j = 0; j < 8; j++) {
#pragma unroll
            for (int c = 0; c < 4; c++) sacc[j][c] *= scale;
            mx0 = fmaxf(mx0, fmaxf(sacc[j][0], sacc[j][1]));
            mx1 = fmaxf(mx1, fmaxf(sacc[j][2], sacc[j][3]));
        }
        mx0 = fmaxf(mx0, __shfl_xor_sync(0xffffffffu, mx0, 1));
        mx0 = fmaxf(mx0, __shfl_xor_sync(0xffffffffu, mx0, 2));
        mx1 = fmaxf(mx1, __shfl_xor_sync(0xffffffffu, mx1, 1));
        mx1 = fmaxf(mx1, __shfl_xor_sync(0xffffffffu, mx1, 2));
        const float mn0 = fmaxf(mrow0, mx0);
        const float mn1 = fmaxf(mrow1, mx1);
        const float f0 = __expf(mrow0 - mn0);
        const float f1 = __expf(mrow1 - mn1);

        float rs0 = 0.0f, rs1 = 0.0f;
#pragma unroll
        for (int j = 0; j < 8; j++) {
            float p0 = __expf(sacc[j][0] - mn0);
            float p1 = __expf(sacc[j][1] - mn0);
            float p2 = __expf(sacc[j][2] - mn1);
            float p3 = __expf(sacc[j][3] - mn1);
            rs0 += p0 + p1;
            rs1 += p2 + p3;
            // hi/lo split store of P
            uint32_t h01 = packbf(p0, p1);
            __nv_bfloat162 hb01 = *reinterpret_cast<__nv_bfloat162*>(&h01);
            uint32_t l01 = packbf(p0 - __bfloat162float(hb01.x), p1 - __bfloat162float(hb01.y));
            uint32_t h23 = packbf(p2, p3);
            __nv_bfloat162 hb23 = *reinterpret_cast<__nv_bfloat162*>(&h23);
            uint32_t l23 = packbf(p2 - __bfloat162float(hb23.x), p3 - __bfloat162float(hb23.y));
            *reinterpret_cast<uint32_t*>(smem + (pRow0Hi - sb) + j * 16) = h01;
            *reinterpret_cast<uint32_t*>(smem + (pRow0Lo - sb) + j * 16) = l01;
            *reinterpret_cast<uint32_t*>(smem + (pRow0Hi - sb) + 8 * STRP + j * 16) = h23;
            *reinterpret_cast<uint32_t*>(smem + (pRow0Lo - sb) + 8 * STRP + j * 16) = l23;
        }
        rs0 += __shfl_xor_sync(0xffffffffu, rs0, 1);
        rs0 += __shfl_xor_sync(0xffffffffu, rs0, 2);
        rs1 += __shfl_xor_sync(0xffffffffu, rs1, 1);
        rs1 += __shfl_xor_sync(0xffffffffu, rs1, 2);
        lrow0 = lrow0 * f0 + rs0;
        lrow1 = lrow1 * f1 + rs1;
        mrow0 = mn0;
        mrow1 = mn1;

        // Rescale O.
#pragma unroll
        for (int j = 0; j < 16; j++) {
            oacc[j][0] *= f0;  oacc[j][1] *= f0;
            oacc[j][2] *= f1;  oacc[j][3] *= f1;
        }
        __syncthreads();   // P visible before PV reads

        // O += P V (3-pass).
#pragma unroll
        for (int kk = 0; kk < 4; kk++) {
            uint32_t PH[4], PL[4];
            LDSM4(PH, aPhi + kk * 32);
            LDSM4(PL, aPlo + kk * 32);
#pragma unroll
            for (int jj = 0; jj < 8; jj++) {
                uint32_t BH[4], BL[4];
                LDSM4(BH, bVhi + jj * (16 * STRP) + kk * 32);
                LDSM4(BL, bVlo + jj * (16 * STRP) + kk * 32);
#pragma unroll
                for (int js = 0; js < 2; js++) {
                    const int j2 = jj * 2 + js, o = js * 2;
                    MMA16816(oacc[j2], PH, BH[o], BH[o + 1]);
                    MMA16816(oacc[j2], PH, BL[o], BL[o + 1]);
                    MMA16816(oacc[j2], PL, BH[o], BH[o + 1]);
                }
            }
        }
        __syncthreads();   // done reading K/V/P before next iteration's stores
    }

    // Epilogue: O /= l, write to [b, s, h*d].
    const float inv0 = 1.0f / lrow0;
    const float inv1 = 1.0f / lrow1;
    const int r0 = m0 + warp * 16 + g;
#pragma unroll
    for (int j2 = 0; j2 < 16; j2++) {
        const int c = j2 * 8 + tig * 2;
        *reinterpret_cast<float2*>(out + ((long long)b * SQ + r0) * HH + head * HD + c) =
            make_float2(oacc[j2][0] * inv0, oacc[j2][1] * inv0);
        *reinterpret_cast<float2*>(out + ((long long)b * SQ + r0 + 8) * HH + head * HD + c) =
            make_float2(oacc[j2][2] * inv1, oacc[j2][3] * inv1);
    }
}

// ---------------------------------------------------------------------------
// Launch
// ---------------------------------------------------------------------------
extern "C" void kernel_launch(void* const* d_in, const int* in_sizes, int n_in,
                              void* d_out, int out_size)
{
    const float* X  = (const float*)d_in[0];
    const float* Wq = (const float*)d_in[1];
    const float* bq = (const float*)d_in[2];
    const float* Wk = (const float*)d_in[3];
    const float* bk = (const float*)d_in[4];
    const float* Wv = (const float*)d_in[5];
    const float* bv = (const float*)d_in[6];
    float* out = (float*)d_out;

    cudaFuncSetAttribute(k_qkv<0>, cudaFuncAttributeMaxDynamicSharedMemorySize, SM_QKV);
    cudaFuncSetAttribute(k_qkv<1>, cudaFuncAttributeMaxDynamicSharedMemorySize, SM_QKV);
    cudaFuncSetAttribute(k_qkv<2>, cudaFuncAttributeMaxDynamicSharedMemorySize, SM_QKV);
    cudaFuncSetAttribute(k_attn,   cudaFuncAttributeMaxDynamicSharedMemorySize, SM_ATTN);

    // 1) QKV projections
    dim3 gProj(HH / 128, (BQ * SQ) / 128);       // (16, 32)
    k_qkv<0><<<gProj, 256, SM_QKV>>>(X, Wq, bq);
    k_qkv<1><<<gProj, 256, SM_QKV>>>(X, Wk, bk);
    k_qkv<2><<<gProj, 256, SM_QKV>>>(X, Wv, bv);

    // 2) RoPE on q and k
    const long long ropeN = (long long)BQ * NH * SQ * (HD / 8);
    dim3 gRope((unsigned)((ropeN + 255) / 256), 2);
    k_rope<<<gRope, 256>>>();

    // 3) Fused flash attention (scores + softmax + PV)
    dim3 gAttn(SQ / 128, BQ * NH);               // (16, 32)
    k_attn<<<gAttn, 256, SM_ATTN>>>(out);
}